// round 5
// baseline (speedup 1.0000x reference)
#include <cuda_runtime.h>
#include <stdint.h>

#define D_MODEL 1024
#define NUM_HEAD 16
#define HEAD_DIM 64
#define BATCH 2
#define SEQ 2048
#define MTOT 4096

__device__ float g_Q[(size_t)MTOT * D_MODEL];
__device__ float g_K[(size_t)MTOT * D_MODEL];
__device__ float g_V[(size_t)MTOT * D_MODEL];
__device__ float g_O[(size_t)MTOT * D_MODEL];
__device__ float g_X[(size_t)MTOT * D_MODEL];          // tf32-rounded x
__device__ float g_W[(size_t)4 * D_MODEL * D_MODEL];   // tf32-rounded Wq,Wk,Wv,Wo

__device__ __forceinline__ uint32_t f2tf(float x) {
    uint32_t r;
    asm("cvt.rna.tf32.f32 %0, %1;" : "=r"(r) : "f"(x));
    return r;
}
__device__ __forceinline__ float ex2(float x) {
    float y;
    asm("ex2.approx.ftz.f32 %0, %1;" : "=f"(y) : "f"(x));
    return y;
}

__device__ __forceinline__ void mma_m16n8k8(float d[4], const uint32_t a[4],
                                            const uint32_t b[2], const float c[4]) {
    asm volatile(
        "mma.sync.aligned.m16n8k8.row.col.f32.tf32.tf32.f32 "
        "{%0,%1,%2,%3}, {%4,%5,%6,%7}, {%8,%9}, {%10,%11,%12,%13};\n"
        : "=f"(d[0]), "=f"(d[1]), "=f"(d[2]), "=f"(d[3])
        : "r"(a[0]), "r"(a[1]), "r"(a[2]), "r"(a[3]),
          "r"(b[0]), "r"(b[1]),
          "f"(c[0]), "f"(c[1]), "f"(c[2]), "f"(c[3]));
}

__device__ __forceinline__ uint32_t s2u(const void* p) {
    return (uint32_t)__cvta_generic_to_shared(p);
}
__device__ __forceinline__ void cp16(uint32_t s, const void* g) {
    asm volatile("cp.async.cg.shared.global [%0], [%1], 16;" :: "r"(s), "l"(g));
}
__device__ __forceinline__ void cpcommit() {
    asm volatile("cp.async.commit_group;");
}
template <int N> __device__ __forceinline__ void cpwait() {
    asm volatile("cp.async.wait_group %0;" :: "n"(N));
}

// ---------------------------------------------------------------------------
// Pre-round x and all W matrices to tf32 (rna). 8M floats total.
// blocks 0..1023: x ; blocks 1024..2047: W[w], 256 blocks each.
// ---------------------------------------------------------------------------
__global__ __launch_bounds__(256) void preround(
    const float* __restrict__ x,
    const float* __restrict__ Wq, const float* __restrict__ Wk,
    const float* __restrict__ Wv, const float* __restrict__ Wo,
    float* __restrict__ Xr, float* __restrict__ Wr)
{
    const int bid = blockIdx.x;
    const float* src;
    float* dst;
    size_t off;
    if (bid < 1024) {
        src = x; dst = Xr; off = (size_t)bid * 4096;
    } else {
        const int w = (bid - 1024) >> 8;
        const int lb = (bid - 1024) & 255;
        src = (w == 0) ? Wq : (w == 1) ? Wk : (w == 2) ? Wv : Wo;
        dst = Wr + (size_t)w * 1048576;
        off = (size_t)lb * 4096;
    }
    const float4* s4 = (const float4*)(src + off);
    float4* d4 = (float4*)(dst + off);
#pragma unroll
    for (int j = 0; j < 4; j++) {
        float4 v = s4[threadIdx.x + j * 256];
        float4 o;
        o.x = __uint_as_float(f2tf(v.x));
        o.y = __uint_as_float(f2tf(v.y));
        o.z = __uint_as_float(f2tf(v.z));
        o.w = __uint_as_float(f2tf(v.w));
        d4[threadIdx.x + j * 256] = o;
    }
}

// ---------------------------------------------------------------------------
// GEMM (NT): C[M,N] = A @ W^T + bias, inputs pre-rounded to tf32.
// 128(M)x64(N)x16 tiles, 8 warps (4m x 2n), warp tile 32x32, 4-stage cp.async.
// 3 blocks/SM. out_scale applied to (acc+bias); round_out rounds stores.
// ---------------------------------------------------------------------------
#define GS 4
#define GSTG 3840  // floats/stage: 128*20 + 64*20

__global__ __launch_bounds__(256, 3) void gemm_tf32(
    const float* __restrict__ A,
    const float* __restrict__ W0, const float* __restrict__ W1,
    const float* __restrict__ W2,
    const float* __restrict__ b0p, const float* __restrict__ b1p,
    const float* __restrict__ b2p,
    float* __restrict__ C0, float* __restrict__ C1, float* __restrict__ C2,
    int round_out)
{
    extern __shared__ float sm[];
    const int z = blockIdx.z;
    const float* W = (z == 0) ? W0 : (z == 1) ? W1 : W2;
    const float* bias = (z == 0) ? b0p : (z == 1) ? b1p : b2p;
    float* C = (z == 0) ? C0 : (z == 1) ? C1 : C2;
    // z==0 (Q projection) folds attention scale * log2e
    const float oscale = (round_out && z == 0) ? 0.18033688011112042f : 1.0f;

    const int tid = threadIdx.x;
    const int warp = tid >> 5, lane = tid & 31;
    const int wm = warp >> 1, wn = warp & 1;
    const int tm = lane >> 2, tk = lane & 3;

    const float* Ab = A + (size_t)(blockIdx.y * 128) * D_MODEL;
    const float* Wb = W + (size_t)(blockIdx.x * 64) * D_MODEL;

    const int lrA = tid >> 1, lkA = (tid & 1) * 8;   // A: 128 rows x 16k
    const int lrB = tid & 63, lkB = (tid >> 6) * 4;  // B: 64 rows x 16k

    float acc[2][4][4];
#pragma unroll
    for (int mt = 0; mt < 2; mt++)
#pragma unroll
        for (int nt = 0; nt < 4; nt++)
#pragma unroll
            for (int i = 0; i < 4; i++) acc[mt][nt][i] = 0.0f;

#pragma unroll
    for (int s = 0; s < GS - 1; s++) {
        float* SA = sm + s * GSTG;
        float* SB = SA + 2560;
        uint32_t sa = s2u(SA + lrA * 20 + lkA);
        cp16(sa, Ab + (size_t)lrA * D_MODEL + s * 16 + lkA);
        cp16(sa + 16, Ab + (size_t)lrA * D_MODEL + s * 16 + lkA + 4);
        cp16(s2u(SB + lrB * 20 + lkB), Wb + (size_t)lrB * D_MODEL + s * 16 + lkB);
        cpcommit();
    }

    const int NIT = D_MODEL / 16;  // 64
    for (int it = 0; it < NIT; it++) {
        cpwait<GS - 2>();
        __syncthreads();

        const int ns = it + GS - 1;
        if (ns < NIT) {
            float* SA = sm + (ns & (GS - 1)) * GSTG;
            float* SB = SA + 2560;
            uint32_t sa = s2u(SA + lrA * 20 + lkA);
            cp16(sa, Ab + (size_t)lrA * D_MODEL + ns * 16 + lkA);
            cp16(sa + 16, Ab + (size_t)lrA * D_MODEL + ns * 16 + lkA + 4);
            cp16(s2u(SB + lrB * 20 + lkB),
                 Wb + (size_t)lrB * D_MODEL + ns * 16 + lkB);
        }
        cpcommit();

        const uint32_t* UA = (const uint32_t*)(sm + (it & (GS - 1)) * GSTG);
        const uint32_t* UB = UA + 2560;

#pragma unroll
        for (int ks = 0; ks < 2; ks++) {
            const int kb = ks * 8;
            uint32_t af[2][4], bf[4][2];
#pragma unroll
            for (int mt = 0; mt < 2; mt++) {
                const int m0 = wm * 32 + mt * 16;
                af[mt][0] = UA[(m0 + tm) * 20 + kb + tk];
                af[mt][1] = UA[(m0 + tm + 8) * 20 + kb + tk];
                af[mt][2] = UA[(m0 + tm) * 20 + kb + tk + 4];
                af[mt][3] = UA[(m0 + tm + 8) * 20 + kb + tk + 4];
            }
#pragma unroll
            for (int nt = 0; nt < 4; nt++) {
                const int n0 = wn * 32 + nt * 8;
                bf[nt][0] = UB[(n0 + tm) * 20 + kb + tk];
                bf[nt][1] = UB[(n0 + tm) * 20 + kb + tk + 4];
            }
#pragma unroll
            for (int mt = 0; mt < 2; mt++)
#pragma unroll
                for (int nt = 0; nt < 4; nt++)
                    mma_m16n8k8(acc[mt][nt], af[mt], bf[nt], acc[mt][nt]);
        }
    }

#pragma unroll
    for (int mt = 0; mt < 2; mt++) {
        const int r0 = blockIdx.y * 128 + wm * 32 + mt * 16 + tm;
#pragma unroll
        for (int nt = 0; nt < 4; nt++) {
            const int col = blockIdx.x * 64 + wn * 32 + nt * 8 + 2 * tk;
            const float bb0 = bias[col], bb1 = bias[col + 1];
            float v0 = (acc[mt][nt][0] + bb0) * oscale;
            float v1 = (acc[mt][nt][1] + bb1) * oscale;
            float v2 = (acc[mt][nt][2] + bb0) * oscale;
            float v3 = (acc[mt][nt][3] + bb1) * oscale;
            if (round_out) {
                v0 = __uint_as_float(f2tf(v0));
                v1 = __uint_as_float(f2tf(v1));
                v2 = __uint_as_float(f2tf(v2));
                v3 = __uint_as_float(f2tf(v3));
            }
            *(float2*)(C + (size_t)r0 * D_MODEL + col) = make_float2(v0, v1);
            *(float2*)(C + (size_t)(r0 + 8) * D_MODEL + col) = make_float2(v2, v3);
        }
    }
}

// ---------------------------------------------------------------------------
// Flash attention: 4 warps, BQ=64 (16 rows/warp), BKT=64.
// Q pre-scaled by 0.125*log2e and tf32-rounded by the Q projection.
// Single-buffered K and V with split cp.async groups:
//   K(i+1) loads during softmax+PV ; V(i+1) loads during next S-MMA.
// Smem floats: Qs[4096] Ps[4096] Ks[64*68] Vs[64*72] = 17152 (68608B) -> 3/SM.
// ---------------------------------------------------------------------------
__global__ __launch_bounds__(128, 3) void flash_tf32(
    const float* __restrict__ Qg, const float* __restrict__ Kg,
    const float* __restrict__ Vg, float* __restrict__ Og)
{
    extern __shared__ float sm[];
    uint32_t* QsU = (uint32_t*)sm;
    uint32_t* PsU = (uint32_t*)(sm + 4096);
    float* Ks = sm + 8192;
    float* Vs = sm + 12544;

    const int tid = threadIdx.x;
    const int warp = tid >> 5, lane = tid & 31;
    const int tm = lane >> 2, tk = lane & 3;
    const int b = blockIdx.y >> 4, h = blockIdx.y & 15;
    const int q0 = blockIdx.x * 64;

    const float* Qb = Qg + (size_t)(b * SEQ + q0) * D_MODEL + h * HEAD_DIM;
    const float* Kb = Kg + (size_t)(b * SEQ) * D_MODEL + h * HEAD_DIM;
    const float* Vb = Vg + (size_t)(b * SEQ) * D_MODEL + h * HEAD_DIM;

    // ---- load Q (pre-scaled, pre-rounded): raw bit copy into swizzle ----
    const int qr = tid & 63;
    const int qh = (tid >> 6) * 32;
#pragma unroll
    for (int i = 0; i < 4; i++) {
        const int kc = qh + i * 8;
        uint4 v0 = *(const uint4*)(Qb + (size_t)qr * D_MODEL + kc);
        uint4 v1 = *(const uint4*)(Qb + (size_t)qr * D_MODEL + kc + 4);
        uint32_t vv[8] = {v0.x, v0.y, v0.z, v0.w, v1.x, v1.y, v1.z, v1.w};
#pragma unroll
        for (int c4 = 0; c4 < 8; c4++) {
            const int k = kc + c4;
            QsU[k * 64 + (qr ^ ((k & 3) << 3))] = vv[c4];
        }
    }

    const int kr = tid & 63;
    const int kh = (tid >> 6) * 32;

    // prologue: group[K0], group[V0]
    {
        uint32_t sk = s2u(Ks + kr * 68 + kh);
        const float* gk = Kb + (size_t)kr * D_MODEL + kh;
#pragma unroll
        for (int i = 0; i < 8; i++) cp16(sk + i * 16, gk + i * 4);
        cpcommit();
        uint32_t sv = s2u(Vs + kr * 72 + kh);
        const float* gv = Vb + (size_t)kr * D_MODEL + kh;
#pragma unroll
        for (int i = 0; i < 8; i++) cp16(sv + i * 16, gv + i * 4);
        cpcommit();
    }

    float s[8][4], acc[8][4], mi[2], li[2];
#pragma unroll
    for (int nt = 0; nt < 8; nt++)
#pragma unroll
        for (int i = 0; i < 4; i++) acc[nt][i] = 0.0f;
    mi[0] = mi[1] = -1e30f;
    li[0] = li[1] = 0.0f;

    const int m0 = warp * 16;
    const int NKT = SEQ / 64;  // 32

    for (int it = 0; it < NKT; it++) {
        cpwait<1>();          // K(it) complete (V group may be in flight)
        __syncthreads();

        // ---- S = Q @ K^T ----
#pragma unroll
        for (int nt = 0; nt < 8; nt++)
#pragma unroll
            for (int i = 0; i < 4; i++) s[nt][i] = 0.0f;

        const uint32_t* KU = (const uint32_t*)Ks;
#pragma unroll
        for (int ks = 0; ks < 8; ks++) {
            const int kb = ks * 8;
            uint32_t af[4], bf[8][2];
            af[0] = QsU[(kb + tk) * 64 + ((m0 + tm) ^ (tk << 3))];
            af[1] = QsU[(kb + tk) * 64 + ((m0 + tm + 8) ^ (tk << 3))];
            af[2] = QsU[(kb + tk + 4) * 64 + ((m0 + tm) ^ (tk << 3))];
            af[3] = QsU[(kb + tk + 4) * 64 + ((m0 + tm + 8) ^ (tk << 3))];
#pragma unroll
            for (int nt = 0; nt < 8; nt++) {
                const int n0 = nt * 8;
                bf[nt][0] = KU[(n0 + tm) * 68 + kb + tk];
                bf[nt][1] = KU[(n0 + tm) * 68 + kb + tk + 4];
            }
#pragma unroll
            for (int nt = 0; nt < 8; nt++)
                mma_m16n8k8(s[nt], af, bf[nt], s[nt]);
        }

        __syncthreads();      // all warps done reading Ks
        if (it + 1 < NKT) {   // K(it+1): overlaps softmax + P + PV
            uint32_t sk = s2u(Ks + kr * 68 + kh);
            const float* gk = Kb + (size_t)((it + 1) * 64 + kr) * D_MODEL + kh;
#pragma unroll
            for (int i = 0; i < 8; i++) cp16(sk + i * 16, gk + i * 4);
        }
        cpcommit();

        // ---- online softmax in log2 domain (scale folded into Q) ----
#pragma unroll
        for (int rh = 0; rh < 2; rh++) {
            float mx = -1e30f;
#pragma unroll
            for (int nt = 0; nt < 8; nt++)
#pragma unroll
                for (int j = 0; j < 2; j++)
                    mx = fmaxf(mx, s[nt][rh * 2 + j]);
            mx = fmaxf(mx, __shfl_xor_sync(0xffffffffu, mx, 1));
            mx = fmaxf(mx, __shfl_xor_sync(0xffffffffu, mx, 2));
            const float mn = fmaxf(mi[rh], mx);
            const float corr = ex2(mi[rh] - mn);
            mi[rh] = mn;
            float sum = 0.0f;
#pragma unroll
            for (int nt = 0; nt < 8; nt++)
#pragma unroll
                for (int j = 0; j < 2; j++) {
                    float p = ex2(s[nt][rh * 2 + j] - mn);
                    s[nt][rh * 2 + j] = p;
                    sum += p;
                }
            sum += __shfl_xor_sync(0xffffffffu, sum, 1);
            sum += __shfl_xor_sync(0xffffffffu, sum, 2);
            li[rh] = li[rh] * corr + sum;
#pragma unroll
            for (int nt = 0; nt < 8; nt++)
#pragma unroll
                for (int j = 0; j < 2; j++)
                    acc[nt][rh * 2 + j] *= corr;
        }

        // ---- P -> smem (a-frag layout [k][m], swizzled, rna) ----
#pragma unroll
        for (int nt = 0; nt < 8; nt++)
#pragma unroll
            for (int rh = 0; rh < 2; rh++)
#pragma unroll
                for (int j = 0; j < 2; j++) {
                    const int r = m0 + tm + rh * 8;
                    const int cN = nt * 8 + 2 * tk + j;
                    PsU[cN * 64 + (r ^ ((cN & 3) << 3))] = f2tf(s[nt][rh * 2 + j]);
                }
        __syncwarp();

        cpwait<1>();          // V(it) complete (K(it+1) may be in flight)
        __syncthreads();

        // ---- O += P @ V ----
        const uint32_t* VU = (const uint32_t*)Vs;
#pragma unroll
        for (int ks = 0; ks < 8; ks++) {
            const int kb = ks * 8;
            uint32_t af[4], bf[8][2];
            af[0] = PsU[(kb + tk) * 64 + ((m0 + tm) ^ (tk << 3))];
            af[1] = PsU[(kb + tk) * 64 + ((m0 + tm + 8) ^ (tk << 3))];
            af[2] = PsU[(kb + tk + 4) * 64 + ((m0 + tm) ^ (tk << 3))];
            af[3] = PsU[(kb + tk + 4) * 64 + ((m0 + tm + 8) ^ (tk << 3))];
#pragma unroll
            for (int nt = 0; nt < 8; nt++) {
                const int n0 = nt * 8;
                bf[nt][0] = VU[(kb + tk) * 72 + n0 + tm];
                bf[nt][1] = VU[(kb + tk + 4) * 72 + n0 + tm];
            }
#pragma unroll
            for (int nt = 0; nt < 8; nt++)
                mma_m16n8k8(acc[nt], af, bf[nt], acc[nt]);
        }

        __syncthreads();      // all warps done reading Vs
        if (it + 1 < NKT) {   // V(it+1): overlaps next S-MMA
            uint32_t sv = s2u(Vs + kr * 72 + kh);
            const float* gv = Vb + (size_t)((it + 1) * 64 + kr) * D_MODEL + kh;
#pragma unroll
            for (int i = 0; i < 8; i++) cp16(sv + i * 16, gv + i * 4);
        }
        cpcommit();
    }

    // ---- epilogue: normalize, round to tf32 for the output projection ----
#pragma unroll
    for (int rh = 0; rh < 2; rh++) {
        const float inv = 1.0f / li[rh];
        const int row = q0 + m0 + tm + rh * 8;
        float* orow = Og + (size_t)(b * SEQ + row) * D_MODEL + h * HEAD_DIM;
#pragma unroll
        for (int nt = 0; nt < 8; nt++) {
            const int col = nt * 8 + 2 * tk;
            float v0 = __uint_as_float(f2tf(acc[nt][rh * 2] * inv));
            float v1 = __uint_as_float(f2tf(acc[nt][rh * 2 + 1] * inv));
            *(float2*)(orow + col) = make_float2(v0, v1);
        }
    }
}

// ---------------------------------------------------------------------------
extern "C" void kernel_launch(void* const* d_in, const int* in_sizes, int n_in,
                              void* d_out, int out_size)
{
    const float* x  = (const float*)d_in[0];
    const float* Wq = (const float*)d_in[1];
    const float* bq = (const float*)d_in[2];
    const float* Wk = (const float*)d_in[3];
    const float* bk = (const float*)d_in[4];
    const float* Wv = (const float*)d_in[5];
    const float* bv = (const float*)d_in[6];
    const float* Wo = (const float*)d_in[7];
    const float* bo = (const float*)d_in[8];
    float* out = (float*)d_out;

    float *Qd, *Kd, *Vd, *Od, *Xd, *Wd;
    cudaGetSymbolAddress((void**)&Qd, g_Q);
    cudaGetSymbolAddress((void**)&Kd, g_K);
    cudaGetSymbolAddress((void**)&Vd, g_V);
    cudaGetSymbolAddress((void**)&Od, g_O);
    cudaGetSymbolAddress((void**)&Xd, g_X);
    cudaGetSymbolAddress((void**)&Wd, g_W);

    static int init = 0;
    if (!init) {
        cudaFuncSetAttribute(gemm_tf32,
                             cudaFuncAttributeMaxDynamicSharedMemorySize, 61440);
        cudaFuncSetAttribute(flash_tf32,
                             cudaFuncAttributeMaxDynamicSharedMemorySize, 68608);
        init = 1;
    }

    preround<<<2048, 256>>>(x, Wq, Wk, Wv, Wo, Xd, Wd);

    float* Wqr = Wd;
    float* Wkr = Wd + 1048576;
    float* Wvr = Wd + 2097152;
    float* Wor = Wd + 3145728;

    dim3 qkv_grid(D_MODEL / 64, MTOT / 128, 3);  // (16, 32, 3)
    gemm_tf32<<<qkv_grid, 256, 61440>>>(Xd, Wqr, Wkr, Wvr, bq, bk, bv,
                                        Qd, Kd, Vd, 1);

    dim3 attn_grid(SEQ / 64, BATCH * NUM_HEAD);  // (32, 32)
    flash_tf32<<<attn_grid, 128, 68608>>>(Qd, Kd, Vd, Od);

    dim3 o_grid(D_MODEL / 64, MTOT / 128, 1);
    gemm_tf32<<<o_grid, 256, 61440>>>(Od, Wor, Wor, Wor, bo, bo, bo,
                                      out, out, out, 0);
}

// round 6
// speedup vs baseline: 1.0842x; 1.0842x over previous
#include <cuda_runtime.h>
#include <stdint.h>

#define D_MODEL 1024
#define NUM_HEAD 16
#define HEAD_DIM 64
#define BATCH 2
#define SEQ 2048
#define MTOT 4096

__device__ float g_Q[(size_t)MTOT * D_MODEL];
__device__ float g_K[(size_t)MTOT * D_MODEL];
__device__ float g_V[(size_t)MTOT * D_MODEL];
__device__ float g_O[(size_t)MTOT * D_MODEL];
__device__ float g_X[(size_t)MTOT * D_MODEL];
__device__ float g_W[(size_t)4 * D_MODEL * D_MODEL];

__device__ __forceinline__ uint32_t f2tf(float x) {
    uint32_t r;
    asm("cvt.rna.tf32.f32 %0, %1;" : "=r"(r) : "f"(x));
    return r;
}
__device__ __forceinline__ float ex2(float x) {
    float y;
    asm("ex2.approx.ftz.f32 %0, %1;" : "=f"(y) : "f"(x));
    return y;
}
__device__ __forceinline__ uint32_t fb(float x) { return __float_as_uint(x); }

__device__ __forceinline__ void mma_m16n8k8(float d[4], const uint32_t a[4],
                                            const uint32_t b[2], const float c[4]) {
    asm volatile(
        "mma.sync.aligned.m16n8k8.row.col.f32.tf32.tf32.f32 "
        "{%0,%1,%2,%3}, {%4,%5,%6,%7}, {%8,%9}, {%10,%11,%12,%13};\n"
        : "=f"(d[0]), "=f"(d[1]), "=f"(d[2]), "=f"(d[3])
        : "r"(a[0]), "r"(a[1]), "r"(a[2]), "r"(a[3]),
          "r"(b[0]), "r"(b[1]),
          "f"(c[0]), "f"(c[1]), "f"(c[2]), "f"(c[3]));
}

__device__ __forceinline__ uint32_t s2u(const void* p) {
    return (uint32_t)__cvta_generic_to_shared(p);
}
__device__ __forceinline__ void cp16(uint32_t s, const void* g) {
    asm volatile("cp.async.cg.shared.global [%0], [%1], 16;" :: "r"(s), "l"(g));
}
__device__ __forceinline__ void cpcommit() {
    asm volatile("cp.async.commit_group;");
}
template <int N> __device__ __forceinline__ void cpwait() {
    asm volatile("cp.async.wait_group %0;" :: "n"(N));
}

// ---------------------------------------------------------------------------
// Pre-round x and all W matrices to tf32 (rna).
// ---------------------------------------------------------------------------
__global__ __launch_bounds__(256) void preround(
    const float* __restrict__ x,
    const float* __restrict__ Wq, const float* __restrict__ Wk,
    const float* __restrict__ Wv, const float* __restrict__ Wo,
    float* __restrict__ Xr, float* __restrict__ Wr)
{
    const int bid = blockIdx.x;
    const float* src;
    float* dst;
    size_t off;
    if (bid < 1024) {
        src = x; dst = Xr; off = (size_t)bid * 4096;
    } else {
        const int w = (bid - 1024) >> 8;
        const int lb = (bid - 1024) & 255;
        src = (w == 0) ? Wq : (w == 1) ? Wk : (w == 2) ? Wv : Wo;
        dst = Wr + (size_t)w * 1048576;
        off = (size_t)lb * 4096;
    }
    const float4* s4 = (const float4*)(src + off);
    float4* d4 = (float4*)(dst + off);
#pragma unroll
    for (int j = 0; j < 4; j++) {
        float4 v = s4[threadIdx.x + j * 256];
        float4 o;
        o.x = __uint_as_float(f2tf(v.x));
        o.y = __uint_as_float(f2tf(v.y));
        o.z = __uint_as_float(f2tf(v.z));
        o.w = __uint_as_float(f2tf(v.w));
        d4[threadIdx.x + j * 256] = o;
    }
}

// ---------------------------------------------------------------------------
// GEMM (NT): C = A @ W^T + bias, pre-rounded tf32 inputs.
// 128x128x16 tiles, 4-stage cp.async, plain [row][k] smem, stride 24.
// Paired LDS.64 fragment loads with logical-k remap (slot tk <- 2tk,
// slot tk+4 <- 2tk+1 on both operands).
// ---------------------------------------------------------------------------
#define GS 4
#define GROW 24
#define GTW (128 * GROW)   // 3072 words per operand tile
#define GSTG (2 * GTW)     // 6144 words per stage

__global__ __launch_bounds__(256) void gemm_tf32(
    const float* __restrict__ A,
    const float* __restrict__ W0, const float* __restrict__ W1,
    const float* __restrict__ W2,
    const float* __restrict__ b0p, const float* __restrict__ b1p,
    const float* __restrict__ b2p,
    float* __restrict__ C0, float* __restrict__ C1, float* __restrict__ C2,
    int round_out)
{
    extern __shared__ float sm[];
    const int z = blockIdx.z;
    const float* W = (z == 0) ? W0 : (z == 1) ? W1 : W2;
    const float* bias = (z == 0) ? b0p : (z == 1) ? b1p : b2p;
    float* C = (z == 0) ? C0 : (z == 1) ? C1 : C2;
    const float oscale = (round_out && z == 0) ? 0.18033688011112042f : 1.0f;

    const int tid = threadIdx.x;
    const int warp = tid >> 5, lane = tid & 31;
    const int wm = warp >> 1, wn = warp & 1;
    const int tm = lane >> 2, tk = lane & 3;

    const float* Ab = A + (size_t)(blockIdx.y * 128) * D_MODEL;
    const float* Wb = W + (size_t)(blockIdx.x * 128) * D_MODEL;

    const int lr = tid >> 1;        // 0..127
    const int lk8 = (tid & 1) * 8;  // 0 or 8

    float acc[2][8][4];
#pragma unroll
    for (int mt = 0; mt < 2; mt++)
#pragma unroll
        for (int nt = 0; nt < 8; nt++)
#pragma unroll
            for (int i = 0; i < 4; i++) acc[mt][nt][i] = 0.0f;

#pragma unroll
    for (int s = 0; s < GS - 1; s++) {
        float* base = sm + s * GSTG;
        uint32_t sa = s2u(base + lr * GROW + lk8);
        uint32_t sb = s2u(base + GTW + lr * GROW + lk8);
        const float* ga = Ab + (size_t)lr * D_MODEL + s * 16 + lk8;
        const float* gw = Wb + (size_t)lr * D_MODEL + s * 16 + lk8;
        cp16(sa, ga); cp16(sa + 16, ga + 4);
        cp16(sb, gw); cp16(sb + 16, gw + 4);
        cpcommit();
    }

    const int NIT = D_MODEL / 16;  // 64
    for (int it = 0; it < NIT; it++) {
        cpwait<GS - 2>();
        __syncthreads();

        const int ns = it + GS - 1;
        if (ns < NIT) {
            float* base = sm + (ns & (GS - 1)) * GSTG;
            uint32_t sa = s2u(base + lr * GROW + lk8);
            uint32_t sb = s2u(base + GTW + lr * GROW + lk8);
            const float* ga = Ab + (size_t)lr * D_MODEL + ns * 16 + lk8;
            const float* gw = Wb + (size_t)lr * D_MODEL + ns * 16 + lk8;
            cp16(sa, ga); cp16(sa + 16, ga + 4);
            cp16(sb, gw); cp16(sb + 16, gw + 4);
        }
        cpcommit();

        const float* FA = sm + (it & (GS - 1)) * GSTG;
        const float* FB = FA + GTW;

#pragma unroll
        for (int ks = 0; ks < 2; ks++) {
            const int kb = ks * 8;
            uint32_t af[2][4], bf[8][2];
#pragma unroll
            for (int mt = 0; mt < 2; mt++) {
                const int m0 = wm * 32 + mt * 16;
                float2 x = *(const float2*)(FA + (m0 + tm) * GROW + kb + 2 * tk);
                float2 y = *(const float2*)(FA + (m0 + tm + 8) * GROW + kb + 2 * tk);
                af[mt][0] = fb(x.x); af[mt][1] = fb(y.x);
                af[mt][2] = fb(x.y); af[mt][3] = fb(y.y);
            }
#pragma unroll
            for (int nt = 0; nt < 8; nt++) {
                const int n0 = wn * 64 + nt * 8;
                float2 zv = *(const float2*)(FB + (n0 + tm) * GROW + kb + 2 * tk);
                bf[nt][0] = fb(zv.x); bf[nt][1] = fb(zv.y);
            }
#pragma unroll
            for (int mt = 0; mt < 2; mt++)
#pragma unroll
                for (int nt = 0; nt < 8; nt++)
                    mma_m16n8k8(acc[mt][nt], af[mt], bf[nt], acc[mt][nt]);
        }
    }

#pragma unroll
    for (int mt = 0; mt < 2; mt++) {
        const int r0 = blockIdx.y * 128 + wm * 32 + mt * 16 + tm;
#pragma unroll
        for (int nt = 0; nt < 8; nt++) {
            const int col = blockIdx.x * 128 + wn * 64 + nt * 8 + 2 * tk;
            const float bb0 = bias[col], bb1 = bias[col + 1];
            float v0 = (acc[mt][nt][0] + bb0) * oscale;
            float v1 = (acc[mt][nt][1] + bb1) * oscale;
            float v2 = (acc[mt][nt][2] + bb0) * oscale;
            float v3 = (acc[mt][nt][3] + bb1) * oscale;
            if (round_out) {
                v0 = __uint_as_float(f2tf(v0));
                v1 = __uint_as_float(f2tf(v1));
                v2 = __uint_as_float(f2tf(v2));
                v3 = __uint_as_float(f2tf(v3));
            }
            *(float2*)(C + (size_t)r0 * D_MODEL + col) = make_float2(v0, v1);
            *(float2*)(C + (size_t)(r0 + 8) * D_MODEL + col) = make_float2(v2, v3);
        }
    }
}

// ---------------------------------------------------------------------------
// Flash attention: 4 warps, BQ=64, BKT=64, split-group cp.async K/V.
// Plain row-major smem, paired LDS.64 frags via logical-k remap.
//   Qs[64 q][72]  Ps[64 q][72]  Ks[64 key][72]  Vs[64 key][76]
// Total 18688 floats = 74752 B -> 3 blocks/SM.
// ---------------------------------------------------------------------------
__global__ __launch_bounds__(128, 3) void flash_tf32(
    const float* __restrict__ Qg, const float* __restrict__ Kg,
    const float* __restrict__ Vg, float* __restrict__ Og)
{
    extern __shared__ float sm[];
    float* Qs = sm;             // 64*72
    float* Ps = sm + 4608;      // 64*72
    float* Ks = sm + 9216;      // 64*72
    float* Vs = sm + 13824;     // 64*76
    uint32_t* PsU = (uint32_t*)Ps;

    const int tid = threadIdx.x;
    const int warp = tid >> 5, lane = tid & 31;
    const int tm = lane >> 2, tk = lane & 3;
    const int b = blockIdx.y >> 4, h = blockIdx.y & 15;
    const int q0 = blockIdx.x * 64;

    const float* Qb = Qg + (size_t)(b * SEQ + q0) * D_MODEL + h * HEAD_DIM;
    const float* Kb = Kg + (size_t)(b * SEQ) * D_MODEL + h * HEAD_DIM;
    const float* Vb = Vg + (size_t)(b * SEQ) * D_MODEL + h * HEAD_DIM;

    // ---- Q tile: direct row-major copy (pre-scaled & pre-rounded) ----
    const int qr = tid & 63;
    const int qh = (tid >> 6) * 32;
#pragma unroll
    for (int i = 0; i < 4; i++) {
        const int kc = qh + i * 8;
        float4 v0 = *(const float4*)(Qb + (size_t)qr * D_MODEL + kc);
        float4 v1 = *(const float4*)(Qb + (size_t)qr * D_MODEL + kc + 4);
        *(float4*)(Qs + qr * 72 + kc) = v0;
        *(float4*)(Qs + qr * 72 + kc + 4) = v1;
    }

    const int kr = tid >> 1;        // 0..63
    const int kh = (tid & 1) * 32;  // 0 or 32

    // prologue: group[K0], group[V0]
    {
        uint32_t sk = s2u(Ks + kr * 72 + kh);
        const float* gk = Kb + (size_t)kr * D_MODEL + kh;
#pragma unroll
        for (int i = 0; i < 8; i++) cp16(sk + i * 16, gk + i * 4);
        cpcommit();
        uint32_t sv = s2u(Vs + kr * 76 + kh);
        const float* gv = Vb + (size_t)kr * D_MODEL + kh;
#pragma unroll
        for (int i = 0; i < 8; i++) cp16(sv + i * 16, gv + i * 4);
        cpcommit();
    }

    float s[8][4], acc[8][4], mi[2], li[2];
#pragma unroll
    for (int nt = 0; nt < 8; nt++)
#pragma unroll
        for (int i = 0; i < 4; i++) acc[nt][i] = 0.0f;
    mi[0] = mi[1] = -1e30f;
    li[0] = li[1] = 0.0f;

    const int m0 = warp * 16;
    const int NKT = SEQ / 64;  // 32

    for (int it = 0; it < NKT; it++) {
        cpwait<1>();          // K(it) done
        __syncthreads();

        // ---- S = Q @ K^T ----
#pragma unroll
        for (int nt = 0; nt < 8; nt++)
#pragma unroll
            for (int i = 0; i < 4; i++) s[nt][i] = 0.0f;

#pragma unroll
        for (int ks = 0; ks < 8; ks++) {
            const int kb = ks * 8;
            uint32_t af[4], bf[8][2];
            float2 x = *(const float2*)(Qs + (m0 + tm) * 72 + kb + 2 * tk);
            float2 y = *(const float2*)(Qs + (m0 + tm + 8) * 72 + kb + 2 * tk);
            af[0] = fb(x.x); af[1] = fb(y.x); af[2] = fb(x.y); af[3] = fb(y.y);
#pragma unroll
            for (int nt = 0; nt < 8; nt++) {
                float2 zv = *(const float2*)(Ks + (nt * 8 + tm) * 72 + kb + 2 * tk);
                bf[nt][0] = fb(zv.x); bf[nt][1] = fb(zv.y);
            }
#pragma unroll
            for (int nt = 0; nt < 8; nt++)
                mma_m16n8k8(s[nt], af, bf[nt], s[nt]);
        }

        __syncthreads();      // Ks reads done
        if (it + 1 < NKT) {   // K(it+1) overlaps softmax + PV
            uint32_t sk = s2u(Ks + kr * 72 + kh);
            const float* gk = Kb + (size_t)((it + 1) * 64 + kr) * D_MODEL + kh;
#pragma unroll
            for (int i = 0; i < 8; i++) cp16(sk + i * 16, gk + i * 4);
        }
        cpcommit();

        // ---- online softmax (log2 domain; scale folded into Q) ----
#pragma unroll
        for (int rh = 0; rh < 2; rh++) {
            float mx = -1e30f;
#pragma unroll
            for (int nt = 0; nt < 8; nt++)
#pragma unroll
                for (int j = 0; j < 2; j++)
                    mx = fmaxf(mx, s[nt][rh * 2 + j]);
            mx = fmaxf(mx, __shfl_xor_sync(0xffffffffu, mx, 1));
            mx = fmaxf(mx, __shfl_xor_sync(0xffffffffu, mx, 2));
            const float mn = fmaxf(mi[rh], mx);
            const float corr = ex2(mi[rh] - mn);
            mi[rh] = mn;
            float sum = 0.0f;
#pragma unroll
            for (int nt = 0; nt < 8; nt++)
#pragma unroll
                for (int j = 0; j < 2; j++) {
                    float p = ex2(s[nt][rh * 2 + j] - mn);
                    s[nt][rh * 2 + j] = p;
                    sum += p;
                }
            sum += __shfl_xor_sync(0xffffffffu, sum, 1);
            sum += __shfl_xor_sync(0xffffffffu, sum, 2);
            li[rh] = li[rh] * corr + sum;
#pragma unroll
            for (int nt = 0; nt < 8; nt++)
#pragma unroll
                for (int j = 0; j < 2; j++)
                    acc[nt][rh * 2 + j] *= corr;
        }

        // ---- P -> smem: row-major [q][key], paired STS.64, rna ----
#pragma unroll
        for (int nt = 0; nt < 8; nt++)
#pragma unroll
            for (int rh = 0; rh < 2; rh++) {
                const int r = m0 + tm + rh * 8;
                *(uint2*)(PsU + r * 72 + nt * 8 + 2 * tk) =
                    make_uint2(f2tf(s[nt][rh * 2]), f2tf(s[nt][rh * 2 + 1]));
            }
        __syncwarp();

        cpwait<1>();          // V(it) done
        __syncthreads();

        // ---- O += P @ V ----
#pragma unroll
        for (int ks = 0; ks < 8; ks++) {
            const int kb = ks * 8;
            uint32_t af[4], bf[8][2];
            uint2 x = *(const uint2*)(PsU + (m0 + tm) * 72 + kb + 2 * tk);
            uint2 y = *(const uint2*)(PsU + (m0 + tm + 8) * 72 + kb + 2 * tk);
            af[0] = x.x; af[1] = y.x; af[2] = x.y; af[3] = y.y;
#pragma unroll
            for (int nt = 0; nt < 8; nt++) {
                bf[nt][0] = fb(Vs[(kb + 2 * tk) * 76 + nt * 8 + tm]);
                bf[nt][1] = fb(Vs[(kb + 2 * tk + 1) * 76 + nt * 8 + tm]);
            }
#pragma unroll
            for (int nt = 0; nt < 8; nt++)
                mma_m16n8k8(acc[nt], af, bf[nt], acc[nt]);
        }

        __syncthreads();      // Vs reads done
        if (it + 1 < NKT) {   // V(it+1) overlaps next S-MMA
            uint32_t sv = s2u(Vs + kr * 76 + kh);
            const float* gv = Vb + (size_t)((it + 1) * 64 + kr) * D_MODEL + kh;
#pragma unroll
            for (int i = 0; i < 8; i++) cp16(sv + i * 16, gv + i * 4);
        }
        cpcommit();
    }

    // ---- epilogue ----
#pragma unroll
    for (int rh = 0; rh < 2; rh++) {
        const float inv = 1.0f / li[rh];
        const int row = q0 + m0 + tm + rh * 8;
        float* orow = Og + (size_t)(b * SEQ + row) * D_MODEL + h * HEAD_DIM;
#pragma unroll
        for (int nt = 0; nt < 8; nt++) {
            const int col = nt * 8 + 2 * tk;
            float v0 = __uint_as_float(f2tf(acc[nt][rh * 2] * inv));
            float v1 = __uint_as_float(f2tf(acc[nt][rh * 2 + 1] * inv));
            *(float2*)(orow + col) = make_float2(v0, v1);
        }
    }
}

// ---------------------------------------------------------------------------
extern "C" void kernel_launch(void* const* d_in, const int* in_sizes, int n_in,
                              void* d_out, int out_size)
{
    const float* x  = (const float*)d_in[0];
    const float* Wq = (const float*)d_in[1];
    const float* bq = (const float*)d_in[2];
    const float* Wk = (const float*)d_in[3];
    const float* bk = (const float*)d_in[4];
    const float* Wv = (const float*)d_in[5];
    const float* bv = (const float*)d_in[6];
    const float* Wo = (const float*)d_in[7];
    const float* bo = (const float*)d_in[8];
    float* out = (float*)d_out;

    float *Qd, *Kd, *Vd, *Od, *Xd, *Wd;
    cudaGetSymbolAddress((void**)&Qd, g_Q);
    cudaGetSymbolAddress((void**)&Kd, g_K);
    cudaGetSymbolAddress((void**)&Vd, g_V);
    cudaGetSymbolAddress((void**)&Od, g_O);
    cudaGetSymbolAddress((void**)&Xd, g_X);
    cudaGetSymbolAddress((void**)&Wd, g_W);

    static int init = 0;
    if (!init) {
        cudaFuncSetAttribute(gemm_tf32,
                             cudaFuncAttributeMaxDynamicSharedMemorySize, 98304);
        cudaFuncSetAttribute(flash_tf32,
                             cudaFuncAttributeMaxDynamicSharedMemorySize, 74752);
        init = 1;
    }

    preround<<<2048, 256>>>(x, Wq, Wk, Wv, Wo, Xd, Wd);

    float* Wqr = Wd;
    float* Wkr = Wd + 1048576;
    float* Wvr = Wd + 2097152;
    float* Wor = Wd + 3145728;

    dim3 qkv_grid(D_MODEL / 128, MTOT / 128, 3);  // (8, 32, 3)
    gemm_tf32<<<qkv_grid, 256, 98304>>>(Xd, Wqr, Wkr, Wvr, bq, bk, bv,
                                        Qd, Kd, Vd, 1);

    dim3 attn_grid(SEQ / 64, BATCH * NUM_HEAD);  // (32, 32)
    flash_tf32<<<attn_grid, 128, 74752>>>(Qd, Kd, Vd, Od);

    dim3 o_grid(D_MODEL / 128, MTOT / 128, 1);
    gemm_tf32<<<o_grid, 256, 98304>>>(Od, Wor, Wor, Wor, bo, bo, bo,
                                      out, out, out, 0);
}

// round 7
// speedup vs baseline: 1.3317x; 1.2284x over previous
#include <cuda_runtime.h>
#include <stdint.h>

#define D_MODEL 1024
#define NUM_HEAD 16
#define HEAD_DIM 64
#define BATCH 2
#define SEQ 2048
#define MTOT 4096

__device__ float g_Q[(size_t)MTOT * D_MODEL];
__device__ float g_K[(size_t)MTOT * D_MODEL];
__device__ float g_V[(size_t)MTOT * D_MODEL];
__device__ float g_O[(size_t)MTOT * D_MODEL];
__device__ float g_X[(size_t)MTOT * D_MODEL];
__device__ float g_W[(size_t)4 * D_MODEL * D_MODEL];

__device__ __forceinline__ uint32_t f2tf(float x) {
    uint32_t r;
    asm("cvt.rna.tf32.f32 %0, %1;" : "=r"(r) : "f"(x));
    return r;
}
__device__ __forceinline__ float ex2(float x) {
    float y;
    asm("ex2.approx.ftz.f32 %0, %1;" : "=f"(y) : "f"(x));
    return y;
}
__device__ __forceinline__ uint32_t fb(float x) { return __float_as_uint(x); }

__device__ __forceinline__ void mma_m16n8k8(float d[4], const uint32_t a[4],
                                            const uint32_t b[2], const float c[4]) {
    asm volatile(
        "mma.sync.aligned.m16n8k8.row.col.f32.tf32.tf32.f32 "
        "{%0,%1,%2,%3}, {%4,%5,%6,%7}, {%8,%9}, {%10,%11,%12,%13};\n"
        : "=f"(d[0]), "=f"(d[1]), "=f"(d[2]), "=f"(d[3])
        : "r"(a[0]), "r"(a[1]), "r"(a[2]), "r"(a[3]),
          "r"(b[0]), "r"(b[1]),
          "f"(c[0]), "f"(c[1]), "f"(c[2]), "f"(c[3]));
}

__device__ __forceinline__ uint32_t s2u(const void* p) {
    return (uint32_t)__cvta_generic_to_shared(p);
}
__device__ __forceinline__ void cp16(uint32_t s, const void* g) {
    asm volatile("cp.async.cg.shared.global [%0], [%1], 16;" :: "r"(s), "l"(g));
}
__device__ __forceinline__ void cpcommit() {
    asm volatile("cp.async.commit_group;");
}
template <int N> __device__ __forceinline__ void cpwait() {
    asm volatile("cp.async.wait_group %0;" :: "n"(N));
}

// ---------------------------------------------------------------------------
__global__ __launch_bounds__(256) void preround(
    const float* __restrict__ x,
    const float* __restrict__ Wq, const float* __restrict__ Wk,
    const float* __restrict__ Wv, const float* __restrict__ Wo,
    float* __restrict__ Xr, float* __restrict__ Wr)
{
    const int bid = blockIdx.x;
    const float* src;
    float* dst;
    size_t off;
    if (bid < 1024) {
        src = x; dst = Xr; off = (size_t)bid * 4096;
    } else {
        const int w = (bid - 1024) >> 8;
        const int lb = (bid - 1024) & 255;
        src = (w == 0) ? Wq : (w == 1) ? Wk : (w == 2) ? Wv : Wo;
        dst = Wr + (size_t)w * 1048576;
        off = (size_t)lb * 4096;
    }
    const float4* s4 = (const float4*)(src + off);
    float4* d4 = (float4*)(dst + off);
#pragma unroll
    for (int j = 0; j < 4; j++) {
        float4 v = s4[threadIdx.x + j * 256];
        float4 o;
        o.x = __uint_as_float(f2tf(v.x));
        o.y = __uint_as_float(f2tf(v.y));
        o.z = __uint_as_float(f2tf(v.z));
        o.w = __uint_as_float(f2tf(v.w));
        d4[threadIdx.x + j * 256] = o;
    }
}

// ---------------------------------------------------------------------------
// GEMM (NT): 128x128x16 tiles, 4-stage cp.async, stage-unrolled main loop so
// every smem address is base_ptr + immediate. Stride-24 rows (conflict-free
// LDS.64 per 16-lane phase). Logical-k remap paired fragment loads.
// ---------------------------------------------------------------------------
#define GROW 24
#define GTW (128 * GROW)       // 3072 words per operand tile
#define GSTG (2 * GTW)         // 6144 words per stage

__global__ __launch_bounds__(256) void gemm_tf32(
    const float* __restrict__ A,
    const float* __restrict__ W0, const float* __restrict__ W1,
    const float* __restrict__ W2,
    const float* __restrict__ b0p, const float* __restrict__ b1p,
    const float* __restrict__ b2p,
    float* __restrict__ C0, float* __restrict__ C1, float* __restrict__ C2,
    int round_out)
{
    extern __shared__ float smf[];
    const int z = blockIdx.z;
    const float* W = (z == 0) ? W0 : (z == 1) ? W1 : W2;
    const float* bias = (z == 0) ? b0p : (z == 1) ? b1p : b2p;
    float* C = (z == 0) ? C0 : (z == 1) ? C1 : C2;
    const float oscale = (round_out && z == 0) ? 0.18033688011112042f : 1.0f;

    const int tid = threadIdx.x;
    const int warp = tid >> 5, lane = tid & 31;
    const int wm = warp >> 1, wn = warp & 1;
    const int tm = lane >> 2, tk = lane & 3;

    const float* Ab = A + (size_t)(blockIdx.y * 128) * D_MODEL;
    const float* Wb = W + (size_t)(blockIdx.x * 128) * D_MODEL;

    const int lr = tid >> 1;
    const int lk8 = (tid & 1) * 8;

    // fixed loader addresses (smem byte, global float*)
    const uint32_t sA = s2u(smf + lr * GROW + lk8);
    const uint32_t sB = sA + GTW * 4;
    const float* gA = Ab + (size_t)lr * D_MODEL + lk8;
    const float* gW = Wb + (size_t)lr * D_MODEL + lk8;

    // fixed fragment base pointers
    const float* pa0 = smf + (wm * 32 + tm) * GROW + 2 * tk;
    const float* pb0 = smf + GTW + (wn * 64 + tm) * GROW + 2 * tk;

    float acc[2][8][4];
#pragma unroll
    for (int mt = 0; mt < 2; mt++)
#pragma unroll
        for (int nt = 0; nt < 8; nt++)
#pragma unroll
            for (int i = 0; i < 4; i++) acc[mt][nt][i] = 0.0f;

    // prologue: stages 0..2 -> bufs 0..2
#pragma unroll
    for (int s = 0; s < 3; s++) {
        cp16(sA + s * GSTG * 4, gA + s * 16);
        cp16(sA + s * GSTG * 4 + 16, gA + s * 16 + 4);
        cp16(sB + s * GSTG * 4, gW + s * 16);
        cp16(sB + s * GSTG * 4 + 16, gW + s * 16 + 4);
        cpcommit();
    }

#define GEMM_STAGE(SBUF, LBUF, KO, DOLOAD)                                    \
    {                                                                          \
        cpwait<2>();                                                           \
        __syncthreads();                                                       \
        if (DOLOAD) {                                                          \
            cp16(sA + (LBUF) * GSTG * 4, gA + (KO));                           \
            cp16(sA + (LBUF) * GSTG * 4 + 16, gA + (KO) + 4);                  \
            cp16(sB + (LBUF) * GSTG * 4, gW + (KO));                           \
            cp16(sB + (LBUF) * GSTG * 4 + 16, gW + (KO) + 4);                  \
        }                                                                      \
        cpcommit();                                                            \
        const float* FA = pa0 + (SBUF) * GSTG;                                 \
        const float* FB = pb0 + (SBUF) * GSTG;                                 \
        _Pragma("unroll")                                                      \
        for (int ks = 0; ks < 2; ks++) {                                       \
            const int kb = ks * 8;                                             \
            uint32_t af[2][4], bf[8][2];                                       \
            {                                                                  \
                float2 x0 = *(const float2*)(FA + kb);                         \
                float2 y0 = *(const float2*)(FA + 192 + kb);                   \
                af[0][0] = fb(x0.x); af[0][1] = fb(y0.x);                      \
                af[0][2] = fb(x0.y); af[0][3] = fb(y0.y);                      \
                float2 x1 = *(const float2*)(FA + 384 + kb);                   \
                float2 y1 = *(const float2*)(FA + 576 + kb);                   \
                af[1][0] = fb(x1.x); af[1][1] = fb(y1.x);                      \
                af[1][2] = fb(x1.y); af[1][3] = fb(y1.y);                      \
            }                                                                  \
            _Pragma("unroll")                                                  \
            for (int nt = 0; nt < 8; nt++) {                                   \
                float2 zv = *(const float2*)(FB + nt * 192 + kb);              \
                bf[nt][0] = fb(zv.x); bf[nt][1] = fb(zv.y);                    \
            }                                                                  \
            _Pragma("unroll")                                                  \
            for (int mt = 0; mt < 2; mt++)                                     \
                _Pragma("unroll")                                              \
                for (int nt = 0; nt < 8; nt++)                                 \
                    mma_m16n8k8(acc[mt][nt], af[mt], bf[nt], acc[mt][nt]);     \
        }                                                                      \
    }

    int koc = 48;
    for (int c = 0; c < 15; c++) {
        GEMM_STAGE(0, 3, koc, 1)
        GEMM_STAGE(1, 0, koc + 16, 1)
        GEMM_STAGE(2, 1, koc + 32, 1)
        GEMM_STAGE(3, 2, koc + 48, 1)
        koc += 64;
    }
    GEMM_STAGE(0, 3, koc, 1)     // stage 60, loads stage 63 (ko=1008)
    GEMM_STAGE(1, 0, 0, 0)
    GEMM_STAGE(2, 0, 0, 0)
    GEMM_STAGE(3, 0, 0, 0)
#undef GEMM_STAGE

#pragma unroll
    for (int mt = 0; mt < 2; mt++) {
        const int r0 = blockIdx.y * 128 + wm * 32 + mt * 16 + tm;
#pragma unroll
        for (int nt = 0; nt < 8; nt++) {
            const int col = blockIdx.x * 128 + wn * 64 + nt * 8 + 2 * tk;
            const float bb0 = bias[col], bb1 = bias[col + 1];
            float v0 = (acc[mt][nt][0] + bb0) * oscale;
            float v1 = (acc[mt][nt][1] + bb1) * oscale;
            float v2 = (acc[mt][nt][2] + bb0) * oscale;
            float v3 = (acc[mt][nt][3] + bb1) * oscale;
            if (round_out) {
                v0 = __uint_as_float(f2tf(v0));
                v1 = __uint_as_float(f2tf(v1));
                v2 = __uint_as_float(f2tf(v2));
                v3 = __uint_as_float(f2tf(v3));
            }
            *(float2*)(C + (size_t)r0 * D_MODEL + col) = make_float2(v0, v1);
            *(float2*)(C + (size_t)(r0 + 8) * D_MODEL + col) = make_float2(v2, v3);
        }
    }
}

// ---------------------------------------------------------------------------
// Flash attention: 8 warps, BQ=128 (16 q-rows/warp), BKT=64, split-group
// cp.async K/V, all smem addresses base_ptr + immediate.
//   Qs[128][72]  Ps[128][72]  Ks[64][72]  Vs[64][76]  = 27904 words (111616 B)
// 2 blocks/SM.
// ---------------------------------------------------------------------------
__global__ __launch_bounds__(256, 2) void flash_tf32(
    const float* __restrict__ Qg, const float* __restrict__ Kg,
    const float* __restrict__ Vg, float* __restrict__ Og)
{
    extern __shared__ float sm[];
    float* Qs = sm;              // 128*72
    float* Ps = sm + 9216;       // 128*72
    float* Ks = sm + 18432;      // 64*72
    float* Vs = sm + 23040;      // 64*76

    const int tid = threadIdx.x;
    const int warp = tid >> 5, lane = tid & 31;
    const int tm = lane >> 2, tk = lane & 3;
    const int b = blockIdx.y >> 4, h = blockIdx.y & 15;
    const int q0 = blockIdx.x * 128;

    const float* Qb = Qg + (size_t)(b * SEQ + q0) * D_MODEL + h * HEAD_DIM;
    const float* Kb = Kg + (size_t)(b * SEQ) * D_MODEL + h * HEAD_DIM;
    const float* Vb = Vg + (size_t)(b * SEQ) * D_MODEL + h * HEAD_DIM;

    // ---- Q tile: row-major copy (pre-scaled & pre-rounded upstream) ----
    {
        const int qr = tid & 127;
        const int qh = (tid >> 7) * 32;
#pragma unroll
        for (int i = 0; i < 4; i++) {
            const int kc = qh + i * 8;
            float4 v0 = *(const float4*)(Qb + (size_t)qr * D_MODEL + kc);
            float4 v1 = *(const float4*)(Qb + (size_t)qr * D_MODEL + kc + 4);
            *(float4*)(Qs + qr * 72 + kc) = v0;
            *(float4*)(Qs + qr * 72 + kc + 4) = v1;
        }
    }

    // ---- K/V loader: fixed addresses ----
    const int kr = tid >> 2;
    const int kc2 = (tid & 3) * 16;
    const uint32_t sK = s2u(Ks + kr * 72 + kc2);
    const uint32_t sV = s2u(Vs + kr * 76 + kc2);
    const float* gK = Kb + (size_t)kr * D_MODEL + kc2;
    const float* gV = Vb + (size_t)kr * D_MODEL + kc2;

    cp16(sK, gK); cp16(sK + 16, gK + 4);
    cp16(sK + 32, gK + 8); cp16(sK + 48, gK + 12);
    cpcommit();
    cp16(sV, gV); cp16(sV + 16, gV + 4);
    cp16(sV + 32, gV + 8); cp16(sV + 48, gV + 12);
    cpcommit();
    gK += 65536;  // 64 rows * 1024
    gV += 65536;

    // ---- fixed fragment base pointers ----
    const float* pQ = Qs + (warp * 16 + tm) * 72 + 2 * tk;
    float* pP = Ps + (warp * 16 + tm) * 72 + 2 * tk;
    uint32_t* pPu = (uint32_t*)pP;
    const float* pK = Ks + tm * 72 + 2 * tk;
    const float* pV = Vs + 2 * tk * 76 + tm;

    float s[8][4], acc[8][4], mi[2], li[2];
#pragma unroll
    for (int nt = 0; nt < 8; nt++)
#pragma unroll
        for (int i = 0; i < 4; i++) acc[nt][i] = 0.0f;
    mi[0] = mi[1] = -1e30f;
    li[0] = li[1] = 0.0f;

    const int NKT = SEQ / 64;  // 32

    for (int it = 0; it < NKT; it++) {
        cpwait<1>();          // K(it) done
        __syncthreads();

        // ---- S = Q @ K^T ----
#pragma unroll
        for (int nt = 0; nt < 8; nt++)
#pragma unroll
            for (int i = 0; i < 4; i++) s[nt][i] = 0.0f;

#pragma unroll
        for (int ks = 0; ks < 8; ks++) {
            const int kb = ks * 8;
            uint32_t af[4], bf[8][2];
            float2 x = *(const float2*)(pQ + kb);
            float2 y = *(const float2*)(pQ + 576 + kb);
            af[0] = fb(x.x); af[1] = fb(y.x); af[2] = fb(x.y); af[3] = fb(y.y);
#pragma unroll
            for (int nt = 0; nt < 8; nt++) {
                float2 zv = *(const float2*)(pK + nt * 576 + kb);
                bf[nt][0] = fb(zv.x); bf[nt][1] = fb(zv.y);
            }
#pragma unroll
            for (int nt = 0; nt < 8; nt++)
                mma_m16n8k8(s[nt], af, bf[nt], s[nt]);
        }

        __syncthreads();      // Ks reads done
        if (it + 1 < NKT) {   // K(it+1) overlaps softmax + PV
            cp16(sK, gK); cp16(sK + 16, gK + 4);
            cp16(sK + 32, gK + 8); cp16(sK + 48, gK + 12);
        }
        cpcommit();
        gK += 65536;

        // ---- online softmax (log2 domain; scale folded into Q) ----
#pragma unroll
        for (int rh = 0; rh < 2; rh++) {
            float mx = -1e30f;
#pragma unroll
            for (int nt = 0; nt < 8; nt++)
#pragma unroll
                for (int j = 0; j < 2; j++)
                    mx = fmaxf(mx, s[nt][rh * 2 + j]);
            mx = fmaxf(mx, __shfl_xor_sync(0xffffffffu, mx, 1));
            mx = fmaxf(mx, __shfl_xor_sync(0xffffffffu, mx, 2));
            const float mn = fmaxf(mi[rh], mx);
            const float corr = ex2(mi[rh] - mn);
            mi[rh] = mn;
            float sum = 0.0f;
#pragma unroll
            for (int nt = 0; nt < 8; nt++)
#pragma unroll
                for (int j = 0; j < 2; j++) {
                    float p = ex2(s[nt][rh * 2 + j] - mn);
                    s[nt][rh * 2 + j] = p;
                    sum += p;
                }
            sum += __shfl_xor_sync(0xffffffffu, sum, 1);
            sum += __shfl_xor_sync(0xffffffffu, sum, 2);
            li[rh] = li[rh] * corr + sum;
#pragma unroll
            for (int nt = 0; nt < 8; nt++)
#pragma unroll
                for (int j = 0; j < 2; j++)
                    acc[nt][rh * 2 + j] *= corr;
        }

        // ---- P -> smem (own warp's rows only; STS.64; rna) ----
#pragma unroll
        for (int nt = 0; nt < 8; nt++)
#pragma unroll
            for (int rh = 0; rh < 2; rh++)
                *(uint2*)(pPu + rh * 576 + nt * 8) =
                    make_uint2(f2tf(s[nt][rh * 2]), f2tf(s[nt][rh * 2 + 1]));
        __syncwarp();

        cpwait<1>();          // V(it) done
        __syncthreads();

        // ---- O += P @ V ----
#pragma unroll
        for (int ks = 0; ks < 8; ks++) {
            const int kb = ks * 8;
            uint32_t af[4], bf[8][2];
            uint2 x = *(const uint2*)(pPu + kb);
            uint2 y = *(const uint2*)(pPu + 576 + kb);
            af[0] = x.x; af[1] = y.x; af[2] = x.y; af[3] = y.y;
#pragma unroll
            for (int nt = 0; nt < 8; nt++) {
                bf[nt][0] = fb(pV[kb * 76 + nt * 8]);
                bf[nt][1] = fb(pV[76 + kb * 76 + nt * 8]);
            }
#pragma unroll
            for (int nt = 0; nt < 8; nt++)
                mma_m16n8k8(acc[nt], af, bf[nt], acc[nt]);
        }

        __syncthreads();      // Vs reads done
        if (it + 1 < NKT) {   // V(it+1) overlaps next S-MMA
            cp16(sV, gV); cp16(sV + 16, gV + 4);
            cp16(sV + 32, gV + 8); cp16(sV + 48, gV + 12);
        }
        cpcommit();
        gV += 65536;
    }

    // ---- epilogue: normalize, round to tf32 for the output projection ----
#pragma unroll
    for (int rh = 0; rh < 2; rh++) {
        const float inv = 1.0f / li[rh];
        const int row = q0 + warp * 16 + tm + rh * 8;
        float* orow = Og + (size_t)(b * SEQ + row) * D_MODEL + h * HEAD_DIM;
#pragma unroll
        for (int nt = 0; nt < 8; nt++) {
            const int col = nt * 8 + 2 * tk;
            float v0 = __uint_as_float(f2tf(acc[nt][rh * 2] * inv));
            float v1 = __uint_as_float(f2tf(acc[nt][rh * 2 + 1] * inv));
            *(float2*)(orow + col) = make_float2(v0, v1);
        }
    }
}

// ---------------------------------------------------------------------------
extern "C" void kernel_launch(void* const* d_in, const int* in_sizes, int n_in,
                              void* d_out, int out_size)
{
    const float* x  = (const float*)d_in[0];
    const float* Wq = (const float*)d_in[1];
    const float* bq = (const float*)d_in[2];
    const float* Wk = (const float*)d_in[3];
    const float* bk = (const float*)d_in[4];
    const float* Wv = (const float*)d_in[5];
    const float* bv = (const float*)d_in[6];
    const float* Wo = (const float*)d_in[7];
    const float* bo = (const float*)d_in[8];
    float* out = (float*)d_out;

    float *Qd, *Kd, *Vd, *Od, *Xd, *Wd;
    cudaGetSymbolAddress((void**)&Qd, g_Q);
    cudaGetSymbolAddress((void**)&Kd, g_K);
    cudaGetSymbolAddress((void**)&Vd, g_V);
    cudaGetSymbolAddress((void**)&Od, g_O);
    cudaGetSymbolAddress((void**)&Xd, g_X);
    cudaGetSymbolAddress((void**)&Wd, g_W);

    static int init = 0;
    if (!init) {
        cudaFuncSetAttribute(gemm_tf32,
                             cudaFuncAttributeMaxDynamicSharedMemorySize, 98304);
        cudaFuncSetAttribute(flash_tf32,
                             cudaFuncAttributeMaxDynamicSharedMemorySize, 111616);
        init = 1;
    }

    preround<<<2048, 256>>>(x, Wq, Wk, Wv, Wo, Xd, Wd);

    float* Wqr = Wd;
    float* Wkr = Wd + 1048576;
    float* Wvr = Wd + 2097152;
    float* Wor = Wd + 3145728;

    dim3 qkv_grid(D_MODEL / 128, MTOT / 128, 3);  // (8, 32, 3)
    gemm_tf32<<<qkv_grid, 256, 98304>>>(Xd, Wqr, Wkr, Wvr, bq, bk, bv,
                                        Qd, Kd, Vd, 1);

    dim3 attn_grid(SEQ / 128, BATCH * NUM_HEAD);  // (16, 32)
    flash_tf32<<<attn_grid, 256, 111616>>>(Qd, Kd, Vd, Od);

    dim3 o_grid(D_MODEL / 128, MTOT / 128, 1);
    gemm_tf32<<<o_grid, 256, 98304>>>(Od, Wor, Wor, Wor, bo, bo, bo,
                                      out, out, out, 0);
}

// round 9
// speedup vs baseline: 2.5993x; 1.9518x over previous
#include <cuda_runtime.h>
#include <cuda_fp16.h>
#include <stdint.h>

#define D_MODEL 1024
#define NUM_HEAD 16
#define HEAD_DIM 64
#define BATCH 2
#define SEQ 2048
#define MTOT 4096

// fp16 scratch
__device__ __half g_Q[(size_t)MTOT * D_MODEL];
__device__ __half g_K[(size_t)MTOT * D_MODEL];
__device__ __half g_VT[(size_t)BATCH * D_MODEL * SEQ];  // [b][d_global][token]
__device__ __half g_O[(size_t)MTOT * D_MODEL];
__device__ __half g_X[(size_t)MTOT * D_MODEL];
__device__ __half g_W[(size_t)4 * D_MODEL * D_MODEL];

__device__ __forceinline__ float ex2(float x) {
    float y;
    asm("ex2.approx.ftz.f32 %0, %1;" : "=f"(y) : "f"(x));
    return y;
}

__device__ __forceinline__ void mma_f16(float d[4], const uint32_t a[4],
                                        const uint32_t b[2], const float c[4]) {
    asm volatile(
        "mma.sync.aligned.m16n8k16.row.col.f32.f16.f16.f32 "
        "{%0,%1,%2,%3}, {%4,%5,%6,%7}, {%8,%9}, {%10,%11,%12,%13};\n"
        : "=f"(d[0]), "=f"(d[1]), "=f"(d[2]), "=f"(d[3])
        : "r"(a[0]), "r"(a[1]), "r"(a[2]), "r"(a[3]),
          "r"(b[0]), "r"(b[1]),
          "f"(c[0]), "f"(c[1]), "f"(c[2]), "f"(c[3]));
}

__device__ __forceinline__ uint32_t s2u(const void* p) {
    return (uint32_t)__cvta_generic_to_shared(p);
}
__device__ __forceinline__ void cp16(uint32_t s, const void* g) {
    asm volatile("cp.async.cg.shared.global [%0], [%1], 16;" :: "r"(s), "l"(g));
}
__device__ __forceinline__ void cpcommit() {
    asm volatile("cp.async.commit_group;");
}
template <int N> __device__ __forceinline__ void cpwait() {
    asm volatile("cp.async.wait_group %0;" :: "n"(N));
}

// ---------------------------------------------------------------------------
// Convert x and the 4 weight matrices to fp16 (rn).
// ---------------------------------------------------------------------------
__global__ __launch_bounds__(256) void preround(
    const float* __restrict__ x,
    const float* __restrict__ Wq, const float* __restrict__ Wk,
    const float* __restrict__ Wv, const float* __restrict__ Wo,
    __half* __restrict__ Xh, __half* __restrict__ Wh)
{
    const int bid = blockIdx.x;
    const float* src;
    __half* dst;
    size_t off;
    if (bid < 1024) {
        src = x; dst = Xh; off = (size_t)bid * 4096;
    } else {
        const int w = (bid - 1024) >> 8;
        const int lb = (bid - 1024) & 255;
        src = (w == 0) ? Wq : (w == 1) ? Wk : (w == 2) ? Wv : Wo;
        dst = Wh + (size_t)w * 1048576;
        off = (size_t)lb * 4096;
    }
    const float4* s4 = (const float4*)(src + off);
    __half2* d2 = (__half2*)(dst + off);
#pragma unroll
    for (int j = 0; j < 4; j++) {
        const int idx = threadIdx.x + j * 256;
        float4 v = s4[idx];
        d2[idx * 2] = __floats2half2_rn(v.x, v.y);
        d2[idx * 2 + 1] = __floats2half2_rn(v.z, v.w);
    }
}

// ---------------------------------------------------------------------------
// fp16 GEMM (NT): C[M,N] = A @ W^T + bias. 128x128x32 tiles, 4-stage cp.async,
// stage-unrolled immediate addressing. Smem rows: 32 halfs data + 16 pad
// (stride 48 halfs = 24 words; fragment phases conflict-free).
// m16n8k16 with logical-k remap: slots (2tk,2tk+1,2tk+8,2tk+9) <- physical
// (4tk..4tk+3) on both operands -> every fragment is one LDS.64.
// Output modes: 0 = fp32, 1 = fp16 * qscale, 2 = fp16, 3 = fp16 transposed VT.
// ---------------------------------------------------------------------------
#define GROWH 48
#define GTH (128 * GROWH)    // 6144 halfs per operand tile
#define GSTGH (2 * GTH)      // 12288 halfs per stage
#define GSTGB (GSTGH * 2)    // 24576 bytes per stage

__global__ __launch_bounds__(256) void gemm_f16(
    const __half* __restrict__ A,
    const __half* __restrict__ W0, const __half* __restrict__ W1,
    const __half* __restrict__ W2,
    const float* __restrict__ b0p, const float* __restrict__ b1p,
    const float* __restrict__ b2p,
    void* __restrict__ C0, void* __restrict__ C1, void* __restrict__ C2,
    int m0_, int m1_, int m2_)
{
    extern __shared__ __half smh[];
    const int z = blockIdx.z;
    const __half* W = (z == 0) ? W0 : (z == 1) ? W1 : W2;
    const float* bias = (z == 0) ? b0p : (z == 1) ? b1p : b2p;
    void* C = (z == 0) ? C0 : (z == 1) ? C1 : C2;
    const int mode = (z == 0) ? m0_ : (z == 1) ? m1_ : m2_;
    const float oscale = (mode == 1) ? 0.18033688011112042f : 1.0f;

    const int tid = threadIdx.x;
    const int warp = tid >> 5, lane = tid & 31;
    const int wm = warp >> 1, wn = warp & 1;
    const int tm = lane >> 2, tk = lane & 3;

    const __half* Ab = A + (size_t)(blockIdx.y * 128) * D_MODEL;
    const __half* Wb = W + (size_t)(blockIdx.x * 128) * D_MODEL;

    const int lr = tid >> 1;         // 0..127
    const int lkh = (tid & 1) * 16;  // half offset 0 or 16

    const uint32_t sAb = s2u(smh + lr * GROWH + lkh);
    const uint32_t sBb = sAb + GTH * 2;
    const __half* gA = Ab + (size_t)lr * D_MODEL + lkh;
    const __half* gW = Wb + (size_t)lr * D_MODEL + lkh;

    const __half* pa0 = smh + (wm * 32 + tm) * GROWH + 4 * tk;
    const __half* pb0 = smh + GTH + (wn * 64 + tm) * GROWH + 4 * tk;

    float acc[2][8][4];
#pragma unroll
    for (int mt = 0; mt < 2; mt++)
#pragma unroll
        for (int nt = 0; nt < 8; nt++)
#pragma unroll
            for (int i = 0; i < 4; i++) acc[mt][nt][i] = 0.0f;

    // prologue: stages 0..2
#pragma unroll
    for (int s = 0; s < 3; s++) {
        cp16(sAb + s * GSTGB, gA + s * 32);
        cp16(sAb + s * GSTGB + 16, gA + s * 32 + 8);
        cp16(sBb + s * GSTGB, gW + s * 32);
        cp16(sBb + s * GSTGB + 16, gW + s * 32 + 8);
        cpcommit();
    }

#define GEMM_STAGE(SBUF, LBUF, KO, DOLOAD)                                    \
    {                                                                          \
        cpwait<2>();                                                           \
        __syncthreads();                                                       \
        if (DOLOAD) {                                                          \
            cp16(sAb + (LBUF) * GSTGB, gA + (KO));                             \
            cp16(sAb + (LBUF) * GSTGB + 16, gA + (KO) + 8);                    \
            cp16(sBb + (LBUF) * GSTGB, gW + (KO));                             \
            cp16(sBb + (LBUF) * GSTGB + 16, gW + (KO) + 8);                    \
        }                                                                      \
        cpcommit();                                                            \
        const __half* FA = pa0 + (SBUF) * GSTGH;                               \
        const __half* FB = pb0 + (SBUF) * GSTGH;                               \
        _Pragma("unroll")                                                      \
        for (int ks = 0; ks < 2; ks++) {                                       \
            uint32_t af[2][4], bf[8][2];                                       \
            {                                                                  \
                uint2 x0 = *(const uint2*)(FA + ks * 16);                      \
                uint2 y0 = *(const uint2*)(FA + 384 + ks * 16);                \
                af[0][0] = x0.x; af[0][1] = y0.x;                              \
                af[0][2] = x0.y; af[0][3] = y0.y;                              \
                uint2 x1 = *(const uint2*)(FA + 768 + ks * 16);                \
                uint2 y1 = *(const uint2*)(FA + 1152 + ks * 16);               \
                af[1][0] = x1.x; af[1][1] = y1.x;                              \
                af[1][2] = x1.y; af[1][3] = y1.y;                              \
            }                                                                  \
            _Pragma("unroll")                                                  \
            for (int nt = 0; nt < 8; nt++) {                                   \
                uint2 zv = *(const uint2*)(FB + nt * 384 + ks * 16);           \
                bf[nt][0] = zv.x; bf[nt][1] = zv.y;                            \
            }                                                                  \
            _Pragma("unroll")                                                  \
            for (int mt = 0; mt < 2; mt++)                                     \
                _Pragma("unroll")                                              \
                for (int nt = 0; nt < 8; nt++)                                 \
                    mma_f16(acc[mt][nt], af[mt], bf[nt], acc[mt][nt]);         \
        }                                                                      \
    }

    int koc = 96;  // stage 3 * 32 halfs
    for (int c = 0; c < 7; c++) {
        GEMM_STAGE(0, 3, koc, 1)
        GEMM_STAGE(1, 0, koc + 32, 1)
        GEMM_STAGE(2, 1, koc + 64, 1)
        GEMM_STAGE(3, 2, koc + 96, 1)
        koc += 128;
    }
    GEMM_STAGE(0, 3, koc, 1)   // stage 28, loads stage 31 (ko = 992)
    GEMM_STAGE(1, 0, 0, 0)
    GEMM_STAGE(2, 0, 0, 0)
    GEMM_STAGE(3, 0, 0, 0)
#undef GEMM_STAGE

    // ---- epilogue ----
#pragma unroll
    for (int mt = 0; mt < 2; mt++) {
        const int r0 = blockIdx.y * 128 + wm * 32 + mt * 16 + tm;
#pragma unroll
        for (int nt = 0; nt < 8; nt++) {
            const int col = blockIdx.x * 128 + wn * 64 + nt * 8 + 2 * tk;
            const float bb0 = bias[col], bb1 = bias[col + 1];
            float v0 = (acc[mt][nt][0] + bb0) * oscale;
            float v1 = (acc[mt][nt][1] + bb1) * oscale;
            float v2 = (acc[mt][nt][2] + bb0) * oscale;
            float v3 = (acc[mt][nt][3] + bb1) * oscale;
            if (mode == 0) {
                float* Cf = (float*)C;
                *(float2*)(Cf + (size_t)r0 * D_MODEL + col) = make_float2(v0, v1);
                *(float2*)(Cf + (size_t)(r0 + 8) * D_MODEL + col) =
                    make_float2(v2, v3);
            } else if (mode != 3) {
                __half* Ch = (__half*)C;
                *(__half2*)(Ch + (size_t)r0 * D_MODEL + col) =
                    __floats2half2_rn(v0, v1);
                *(__half2*)(Ch + (size_t)(r0 + 8) * D_MODEL + col) =
                    __floats2half2_rn(v2, v3);
            } else {
                // VT[b][col][token]
                const int bb = r0 >> 11;
                const int tok = r0 & 2047;
                __half* vb = (__half*)C + ((size_t)(bb * 1024 + col)) * 2048 + tok;
                vb[0] = __float2half_rn(v0);
                vb[2048] = __float2half_rn(v1);
                vb[8] = __float2half_rn(v2);
                vb[2048 + 8] = __float2half_rn(v3);
            }
        }
    }
}

// ---------------------------------------------------------------------------
// fp16 flash attention: 8 warps, BQ=128 (16 q-rows/warp), BKT=64, split-group
// cp.async K/VT, immediate addressing. m16n8k16, 4-chunk logical-k remap.
// Smem halfs (stride 80/row): Qs[128] Ps[128] Ks[64] Vt[64] = 61440 B.
// ---------------------------------------------------------------------------
__global__ __launch_bounds__(256, 2) void flash_f16(
    const __half* __restrict__ Qg, const __half* __restrict__ Kg,
    const __half* __restrict__ VTg, __half* __restrict__ Og)
{
    extern __shared__ __half smh[];
    __half* Qs = smh;            // 128*80
    __half* Ps = smh + 10240;
    __half* Ks = smh + 20480;    // 64*80
    __half* Vt = smh + 25600;

    const int tid = threadIdx.x;
    const int warp = tid >> 5, lane = tid & 31;
    const int tm = lane >> 2, tk = lane & 3;
    const int b = blockIdx.y >> 4, h = blockIdx.y & 15;
    const int q0 = blockIdx.x * 128;

    const __half* Qb = Qg + (size_t)(b * SEQ + q0) * D_MODEL + h * HEAD_DIM;
    const __half* Kb = Kg + (size_t)(b * SEQ) * D_MODEL + h * HEAD_DIM;

    // ---- Q tile via cp.async (group 1) ----
    {
        const int qr = tid >> 1;
        const int qc = (tid & 1) * 32;
        uint32_t sq = s2u(Qs + qr * 80 + qc);
        const __half* gq = Qb + (size_t)qr * D_MODEL + qc;
        cp16(sq, gq); cp16(sq + 16, gq + 8);
        cp16(sq + 32, gq + 16); cp16(sq + 48, gq + 24);
        cpcommit();
    }

    // ---- K/VT loaders: fixed addresses ----
    const int kr = tid >> 2;
    const int kc = (tid & 3) * 16;
    const uint32_t sK = s2u(Ks + kr * 80 + kc);
    const uint32_t sV = s2u(Vt + kr * 80 + kc);
    const __half* gK = Kb + (size_t)kr * D_MODEL + kc;
    const __half* gV = VTg + ((size_t)(b * 1024 + h * HEAD_DIM + kr)) * 2048 + kc;

    cp16(sK, gK); cp16(sK + 16, gK + 8);
    cpcommit();
    cp16(sV, gV); cp16(sV + 16, gV + 8);
    cpcommit();
    gK += 64 * D_MODEL;
    gV += 64;

    // ---- fragment base pointers ----
    const __half* pQ = Qs + (warp * 16 + tm) * 80 + 4 * tk;
    const __half* pP = Ps + (warp * 16 + tm) * 80 + 4 * tk;
    __half* pPst = Ps + (warp * 16 + tm) * 80 + 2 * tk;
    const __half* pK = Ks + tm * 80 + 4 * tk;
    const __half* pV = Vt + tm * 80 + 4 * tk;

    float s[8][4], acc[8][4], mi[2], li[2];
#pragma unroll
    for (int nt = 0; nt < 8; nt++)
#pragma unroll
        for (int i = 0; i < 4; i++) acc[nt][i] = 0.0f;
    mi[0] = mi[1] = -1e30f;
    li[0] = li[1] = 0.0f;

    const int NKT = SEQ / 64;  // 32

    for (int it = 0; it < NKT; it++) {
        cpwait<1>();          // Q + K(it) complete (VT group may be in flight)
        __syncthreads();

        // ---- S = Q @ K^T ----
#pragma unroll
        for (int nt = 0; nt < 8; nt++)
#pragma unroll
            for (int i = 0; i < 4; i++) s[nt][i] = 0.0f;

#pragma unroll
        for (int ks = 0; ks < 4; ks++) {
            uint32_t af[4], bf[8][2];
            uint2 x = *(const uint2*)(pQ + ks * 16);
            uint2 y = *(const uint2*)(pQ + 640 + ks * 16);
            af[0] = x.x; af[1] = y.x; af[2] = x.y; af[3] = y.y;
#pragma unroll
            for (int nt = 0; nt < 8; nt++) {
                uint2 zv = *(const uint2*)(pK + nt * 640 + ks * 16);
                bf[nt][0] = zv.x; bf[nt][1] = zv.y;
            }
#pragma unroll
            for (int nt = 0; nt < 8; nt++)
                mma_f16(s[nt], af, bf[nt], s[nt]);
        }

        __syncthreads();      // Ks reads done
        if (it + 1 < NKT) {   // K(it+1) overlaps softmax + PV
            cp16(sK, gK); cp16(sK + 16, gK + 8);
        }
        cpcommit();
        gK += 64 * D_MODEL;

        // ---- online softmax (log2 domain; scale folded into Q) ----
#pragma unroll
        for (int rh = 0; rh < 2; rh++) {
            float mx = -1e30f;
#pragma unroll
            for (int nt = 0; nt < 8; nt++)
#pragma unroll
                for (int j = 0; j < 2; j++)
                    mx = fmaxf(mx, s[nt][rh * 2 + j]);
            mx = fmaxf(mx, __shfl_xor_sync(0xffffffffu, mx, 1));
            mx = fmaxf(mx, __shfl_xor_sync(0xffffffffu, mx, 2));
            const float mn = fmaxf(mi[rh], mx);
            const float corr = ex2(mi[rh] - mn);
            mi[rh] = mn;
            float sum = 0.0f;
#pragma unroll
            for (int nt = 0; nt < 8; nt++)
#pragma unroll
                for (int j = 0; j < 2; j++) {
                    float p = ex2(s[nt][rh * 2 + j] - mn);
                    s[nt][rh * 2 + j] = p;
                    sum += p;
                }
            sum += __shfl_xor_sync(0xffffffffu, sum, 1);
            sum += __shfl_xor_sync(0xffffffffu, sum, 2);
            li[rh] = li[rh] * corr + sum;
#pragma unroll
            for (int nt = 0; nt < 8; nt++)
#pragma unroll
                for (int j = 0; j < 2; j++)
                    acc[nt][rh * 2 + j] *= corr;
        }

        // ---- P -> smem as fp16 (own rows; STS.32 packed pairs) ----
#pragma unroll
        for (int nt = 0; nt < 8; nt++)
#pragma unroll
            for (int rh = 0; rh < 2; rh++)
                *(__half2*)(pPst + rh * 640 + nt * 8) =
                    __floats2half2_rn(s[nt][rh * 2], s[nt][rh * 2 + 1]);
        __syncwarp();

        cpwait<1>();          // VT(it) complete (K(it+1) in flight)
        __syncthreads();

        // ---- O += P @ V  (B-frags from VT rows = d) ----
#pragma unroll
        for (int ks = 0; ks < 4; ks++) {
            uint32_t af[4], bf[8][2];
            uint2 x = *(const uint2*)(pP + ks * 16);
            uint2 y = *(const uint2*)(pP + 640 + ks * 16);
            af[0] = x.x; af[1] = y.x; af[2] = x.y; af[3] = y.y;
#pragma unroll
            for (int nt = 0; nt < 8; nt++) {
                uint2 zv = *(const uint2*)(pV + nt * 640 + ks * 16);
                bf[nt][0] = zv.x; bf[nt][1] = zv.y;
            }
#pragma unroll
            for (int nt = 0; nt < 8; nt++)
                mma_f16(acc[nt], af, bf[nt], acc[nt]);
        }

        __syncthreads();      // Vt reads done
        if (it + 1 < NKT) {   // VT(it+1) overlaps next S-MMA
            cp16(sV, gV); cp16(sV + 16, gV + 8);
        }
        cpcommit();
        gV += 64;
    }

    // ---- epilogue: normalize, fp16 out ----
#pragma unroll
    for (int rh = 0; rh < 2; rh++) {
        const float inv = 1.0f / li[rh];
        const int row = q0 + warp * 16 + tm + rh * 8;
        __half* orow = Og + (size_t)(b * SEQ + row) * D_MODEL + h * HEAD_DIM;
#pragma unroll
        for (int nt = 0; nt < 8; nt++) {
            const int col = nt * 8 + 2 * tk;
            *(__half2*)(orow + col) =
                __floats2half2_rn(acc[nt][rh * 2] * inv, acc[nt][rh * 2 + 1] * inv);
        }
    }
}

// ---------------------------------------------------------------------------
extern "C" void kernel_launch(void* const* d_in, const int* in_sizes, int n_in,
                              void* d_out, int out_size)
{
    const float* x  = (const float*)d_in[0];
    const float* Wq = (const float*)d_in[1];
    const float* bq = (const float*)d_in[2];
    const float* Wk = (const float*)d_in[3];
    const float* bk = (const float*)d_in[4];
    const float* Wv = (const float*)d_in[5];
    const float* bv = (const float*)d_in[6];
    const float* Wo = (const float*)d_in[7];
    const float* bo = (const float*)d_in[8];
    float* out = (float*)d_out;

    __half *Qd, *Kd, *VTd, *Od, *Xd, *Wd;
    cudaGetSymbolAddress((void**)&Qd, g_Q);
    cudaGetSymbolAddress((void**)&Kd, g_K);
    cudaGetSymbolAddress((void**)&VTd, g_VT);
    cudaGetSymbolAddress((void**)&Od, g_O);
    cudaGetSymbolAddress((void**)&Xd, g_X);
    cudaGetSymbolAddress((void**)&Wd, g_W);

    static int init = 0;
    if (!init) {
        cudaFuncSetAttribute(gemm_f16,
                             cudaFuncAttributeMaxDynamicSharedMemorySize, 98304);
        cudaFuncSetAttribute(flash_f16,
                             cudaFuncAttributeMaxDynamicSharedMemorySize, 61440);
        init = 1;
    }

    preround<<<2048, 256>>>(x, Wq, Wk, Wv, Wo, Xd, Wd);

    __half* Wqh = Wd;
    __half* Wkh = Wd + 1048576;
    __half* Wvh = Wd + 2097152;
    __half* Woh = Wd + 3145728;

    dim3 qkv_grid(D_MODEL / 128, MTOT / 128, 3);  // (8, 32, 3)
    gemm_f16<<<qkv_grid, 256, 98304>>>(Xd, Wqh, Wkh, Wvh, bq, bk, bv,
                                       Qd, Kd, VTd, 1, 2, 3);

    dim3 attn_grid(SEQ / 128, BATCH * NUM_HEAD);  // (16, 32)
    flash_f16<<<attn_grid, 256, 61440>>>(Qd, Kd, VTd, Od);

    dim3 o_grid(D_MODEL / 128, MTOT / 128, 1);    // (8, 32, 1)
    gemm_f16<<<o_grid, 256, 98304>>>(Od, Woh, Woh, Woh, bo, bo, bo,
                                     out, out, out, 0, 0, 0);
}